// round 1
// baseline (speedup 1.0000x reference)
#include <cuda_runtime.h>

// WindowWarp: out[b,t,c] = lerp_u( lerp_s(x) )
// B=256, T=2048, C=64, WARP_SIZE=205, L_MAX=2253
// Fully fused: 4 gathered row reads + 1 write per (b,t).

#define BB 256
#define TT 2048
#define CC 64
#define WSZ 205.0f
#define WSZ_M1 204.0f
#define TM1 2047.0f
#define LMAX_M1 2252.0f

__device__ __forceinline__ float4 lerp4(float4 a, float4 b, float f) {
    float4 r;
    r.x = a.x * (1.0f - f) + b.x * f;
    r.y = a.y * (1.0f - f) + b.y * f;
    r.z = a.z * (1.0f - f) + b.z * f;
    r.w = a.w * (1.0f - f) + b.w * f;
    return r;
}

// warped[j] for one batch: maps j -> source position s, then lerps x rows.
// xb points at this batch's x, already offset by the channel lane; row stride = CC/4 float4s.
__device__ __forceinline__ float4 warped_at(const float4* __restrict__ xb,
                                            float j, float start, float nl) {
    float s;
    float wend = start + nl;
    if (j >= start && j < wend) {
        float denom = fmaxf(nl - 1.0f, 1.0f);
        s = start + (j - start) * WSZ_M1 / denom;   // match JAX op order
    } else if (j >= wend) {
        s = j - nl + WSZ;
    } else {
        s = j;
    }
    s = fminf(fmaxf(s, 0.0f), TM1);
    float p0 = floorf(s);
    float fr = s - p0;
    int i0 = (int)p0;
    int i1 = min(i0 + 1, TT - 1);
    float4 g0 = xb[i0 * (CC / 4)];
    float4 g1 = xb[i1 * (CC / 4)];
    return lerp4(g0, g1, fr);
}

__global__ void __launch_bounds__(256) window_warp_kernel(
    const float* __restrict__ x,
    const float* __restrict__ warp_scales,
    const int*   __restrict__ window_starts,
    float* __restrict__ out)
{
    int b    = blockIdx.y;
    int t    = blockIdx.x * 16 + threadIdx.y;
    int lane = threadIdx.x;          // 0..15, each covers 4 channels

    float scale = __ldg(warp_scales + b);
    float start = (float)__ldg(window_starts + b);
    float nl    = floorf(WSZ * scale);          // new_len
    float Lm1   = ((float)TT - WSZ + nl) - 1.0f;

    // outer resample position
    float u = (float)t * Lm1 / TM1;             // match JAX: mult then divide
    u = fminf(fmaxf(u, 0.0f), Lm1);
    float j0 = floorf(u);
    float fu = u - j0;
    float j1 = fminf(j0 + 1.0f, LMAX_M1);

    const float4* xb = reinterpret_cast<const float4*>(x + (size_t)b * TT * CC) + lane;

    float4 w0 = warped_at(xb, j0, start, nl);
    float4 w1 = warped_at(xb, j1, start, nl);
    float4 r  = lerp4(w0, w1, fu);

    float4* ob = reinterpret_cast<float4*>(out + (size_t)b * TT * CC) + lane;
    ob[t * (CC / 4)] = r;
}

extern "C" void kernel_launch(void* const* d_in, const int* in_sizes, int n_in,
                              void* d_out, int out_size) {
    const float* x      = (const float*)d_in[0];
    const float* scales = (const float*)d_in[1];
    const int*   starts = (const int*)d_in[2];
    float* out = (float*)d_out;

    dim3 block(16, 16);          // 16 float4 lanes x 16 t-rows = 256 threads
    dim3 grid(TT / 16, BB);      // (128, 256)
    window_warp_kernel<<<grid, block>>>(x, scales, starts, out);
}